// round 13
// baseline (speedup 1.0000x reference)
#include <cuda_runtime.h>
#include <cstdint>

// ===========================================================================
// FusionModel via mma.sync m16n8k16 fp16 — R4 GEMM loop verbatim; tail uses
// SCALAR stores (same consumption shape as R4's scalar atomics — no STG.128
// register-quad constraint, which is the suspected spill trigger in R9-R12).
//   H1pre = x @ W1,  x[b,(i*64+j)*64+k] = v1e[b,i]*v2e[b,j]*v3e[b,k]
//   M=256, N=256, K=262144. Grid: 2 mtiles x 74 K-chunks = 148 CTAs (1 wave).
// Tail: scalar STG partials -> k_reduce (74-chunk coalesced sum) -> k_epi.
// ===========================================================================

namespace {
constexpr int BATCH = 256;
constexpr int DIN   = 63;
constexpr int H1    = 256;
constexpr int H2    = 128;
constexpr float EPSV  = 1e-5f;
constexpr float SLOPE = 0.1f;

constexpr int NSLABS  = 4096;
constexpr int NCHUNKS = 74;
constexpr int NT      = 256;

constexpr int SMB_BYTES = 65536;        // B slab: 64k x 256n fp32 (swizzled)
constexpr int SMA_BYTES = 128 * 144;    // A slab: 128 rows x (64 half + pad)
constexpr int SM_B   = 0;               // 2 x 64 KB
constexpr int SM_A   = 2 * SMB_BYTES;   // 131072, 2 x 18432
constexpr int SM_TOTAL = SM_A + 2 * SMA_BYTES;   // 167936 B
constexpr int A_WSTRIDE = 36;           // words per A row (144 B)
}

// per-(chunk,mtile) partial tiles [148][128*256] + reduced H1pre [2][32768]
__device__ float g_part[2 * NCHUNKS * 32768];
__device__ float g_red[2 * 32768];

// ---- helpers --------------------------------------------------------------
__device__ __forceinline__ uint32_t smem_u32(const void* p) {
    uint32_t a;
    asm("{ .reg .u64 t; cvta.to.shared.u64 t, %1; cvt.u32.u64 %0, t; }"
        : "=r"(a) : "l"(p));
    return a;
}
__device__ __forceinline__ uint32_t pkh2(float lo, float hi) {
    uint32_t d;
    asm("cvt.rn.f16x2.f32 %0, %1, %2;" : "=r"(d) : "f"(hi), "f"(lo));
    return d;
}
__device__ __forceinline__ void mma_f16(float* c, const uint32_t* a,
                                        const uint32_t* b) {
    asm volatile(
        "mma.sync.aligned.m16n8k16.row.col.f32.f16.f16.f32 "
        "{%0,%1,%2,%3}, {%4,%5,%6,%7}, {%8,%9}, {%0,%1,%2,%3};"
        : "+f"(c[0]), "+f"(c[1]), "+f"(c[2]), "+f"(c[3])
        : "r"(a[0]), "r"(a[1]), "r"(a[2]), "r"(a[3]), "r"(b[0]), "r"(b[1]));
}
__device__ __forceinline__ void cp16(uint32_t dst, const void* src) {
    asm volatile("cp.async.cg.shared.global [%0], [%1], 16;"
                 :: "r"(dst), "l"(src));
}
#define CP_COMMIT() asm volatile("cp.async.commit_group;" ::: "memory")
#define CP_WAIT1()  asm volatile("cp.async.wait_group 1;" ::: "memory")

// swizzled float index of B[k][n] (k:0..63, n:0..255), xor class (k>>1)&3
__device__ __forceinline__ int bidx(int k, int n) {
    return k * 256 + (((n >> 2) ^ (((k >> 1) & 3) << 1)) << 2) + (n & 3);
}

// ---------------------------------------------------------------------------
__global__ __launch_bounds__(NT, 1)
void k_gemm_mma(const float* __restrict__ v1, const float* __restrict__ v2,
                const float* __restrict__ v3, const float* __restrict__ W1) {
    extern __shared__ char smem[];
    float*    Bsm = (float*)(smem + SM_B);
    uint32_t* Asm = (uint32_t*)(smem + SM_A);   // [2][128 rows][36 words]
    const uint32_t b_u32 = smem_u32(Bsm);

    const int tid = threadIdx.x;
    const int wid = tid >> 5, l = tid & 31;
    const int lq = l >> 2, lr = l & 3;
    const int wm = wid >> 2, wn = wid & 3;
    const int mr = wm * 64, nc = wn * 64;

    const int mtile = blockIdx.x;
    const int chunk = blockIdx.y;
    const int s_lo = (chunk * NSLABS) / NCHUNKS;
    const int s_hi = ((chunk + 1) * NSLABS) / NCHUNKS;

    // A-gen ownership: row tb, k-half h; v3 register-resident
    const int tb = tid >> 1, h = tid & 1;
    const int bg = mtile * 128 + tb;
    float v3r[32];
#pragma unroll
    for (int q = 0; q < 32; ++q) {
        int kk = h * 32 + q;
        v3r[q] = (kk < DIN) ? v3[bg * DIN + kk] : 1.0f;
    }

    // cp ownership: row ck, n-window cq*64
    const int ck = tid & 63;
    const int cq = tid >> 6;

    auto issue = [&](int s, int p) {
        const float* base = W1 + (size_t)s * 64 * H1 + (size_t)ck * H1 + cq * 64;
        uint32_t bb = b_u32 + (uint32_t)p * SMB_BYTES;
#pragma unroll
        for (int it = 0; it < 16; ++it) {
            int ncx = cq * 16 + it;
            uint32_t dst = bb + (uint32_t)((ck * 64 + (ncx ^ (((ck >> 1) & 3) << 1))) * 16);
            cp16(dst, base + it * 4);
        }
        CP_COMMIT();
    };

    issue(s_lo, 0);
    if (s_lo + 1 < s_hi) issue(s_lo + 1, 1);

    float acc[4][8][4];
#pragma unroll
    for (int mt = 0; mt < 4; ++mt)
#pragma unroll
        for (int nt = 0; nt < 8; ++nt)
#pragma unroll
            for (int q = 0; q < 4; ++q) acc[mt][nt][q] = 0.0f;

    for (int s = s_lo; s < s_hi; ++s) {
        const int sl = s - s_lo;
        const int p = sl & 1;
        const float*    Bp = Bsm + p * (SMB_BYTES / 4);
        const uint32_t* Ap = Asm + p * (SMA_BYTES / 4);

        // ---- A gen: fp16 A[row][k] = cvt(s(b) * v3[b,k]) ----
        {
            int i = s >> 6, j = s & 63;
            float ai = (i < DIN) ? __ldg(v1 + bg * DIN + i) : 1.0f;
            float cj = (j < DIN) ? __ldg(v2 + bg * DIN + j) : 1.0f;
            float sv = ai * cj;
            uint32_t* dst = (uint32_t*)(smem + SM_A + p * SMA_BYTES) +
                            tb * A_WSTRIDE + h * 16;
#pragma unroll
            for (int g = 0; g < 4; ++g) {
                uint4 v;
                v.x = pkh2(sv * v3r[g * 8 + 0], sv * v3r[g * 8 + 1]);
                v.y = pkh2(sv * v3r[g * 8 + 2], sv * v3r[g * 8 + 3]);
                v.z = pkh2(sv * v3r[g * 8 + 4], sv * v3r[g * 8 + 5]);
                v.w = pkh2(sv * v3r[g * 8 + 6], sv * v3r[g * 8 + 7]);
                *(uint4*)(dst + g * 4) = v;
            }
        }

        CP_WAIT1();
        __syncthreads();

#pragma unroll
        for (int kk = 0; kk < 4; ++kk) {
            const int kw = kk * 8 + lr;     // word offset within A row
            const int kb = kk * 16;         // k base for B
            uint32_t a[4][4];
#pragma unroll
            for (int mt = 0; mt < 4; ++mt) {
                const uint32_t* ar = Ap + (mr + mt * 16 + lq) * A_WSTRIDE;
                a[mt][0] = ar[kw];
                a[mt][1] = ar[8 * A_WSTRIDE + kw];
                a[mt][2] = ar[kw + 4];
                a[mt][3] = ar[8 * A_WSTRIDE + kw + 4];
            }
            const int k0 = kb + lr * 2;
            uint32_t bfr[8][2];
#pragma unroll
            for (int nt = 0; nt < 8; ++nt) {
                const int n = nc + nt * 8 + lq;
                bfr[nt][0] = pkh2(Bp[bidx(k0, n)],     Bp[bidx(k0 + 1, n)]);
                bfr[nt][1] = pkh2(Bp[bidx(k0 + 8, n)], Bp[bidx(k0 + 9, n)]);
            }
#pragma unroll
            for (int mt = 0; mt < 4; ++mt)
#pragma unroll
                for (int nt = 0; nt < 8; ++nt)
                    mma_f16(acc[mt][nt], a[mt], bfr[nt]);
        }
        __syncthreads();

        if (s + 2 < s_hi) issue(s + 2, p);
    }

    // ---- SCALAR partial store (same consumption shape as R4's atomics) ----
    float* part = g_part + (size_t)(chunk * 2 + mtile) * 32768;
#pragma unroll
    for (int mt = 0; mt < 4; ++mt) {
        const int row = mr + mt * 16 + lq;       // local row within tile
#pragma unroll
        for (int nt = 0; nt < 8; ++nt) {
            const int col = nc + nt * 8 + lr * 2;
            part[row * H1 + col]           = acc[mt][nt][0];
            part[row * H1 + col + 1]       = acc[mt][nt][1];
            part[(row + 8) * H1 + col]     = acc[mt][nt][2];
            part[(row + 8) * H1 + col + 1] = acc[mt][nt][3];
        }
    }
}

// ---------------------------------------------------------------------------
// reduce 74 chunks: g_red[mtile*32768+off] = sum_c g_part[(c*2+mtile)*32768+off]
__global__ __launch_bounds__(1024)
void k_reduce() {
    const int idx = blockIdx.x * 1024 + threadIdx.x;   // 0..65535
    const int mtile = idx >> 15;
    const int off = idx & 32767;
    const float* src = g_part + (size_t)mtile * 32768 + off;
    float x = 0.0f;
#pragma unroll 8
    for (int c = 0; c < NCHUNKS; ++c) x += src[(size_t)c * 65536];
    g_red[idx] = x;
}

// ---------------------------------------------------------------------------
__global__ __launch_bounds__(H1)
void k_epi(const float* __restrict__ b1,  const float* __restrict__ g1,
           const float* __restrict__ be1, const float* __restrict__ rm1,
           const float* __restrict__ rv1, const float* __restrict__ W2,
           const float* __restrict__ b2,  const float* __restrict__ g2,
           const float* __restrict__ be2, const float* __restrict__ rm2,
           const float* __restrict__ rv2, const float* __restrict__ Wc,
           const float* __restrict__ bc,  float* __restrict__ out) {
    __shared__ float h1s[H1];
    __shared__ float red[H2];
    const int b = blockIdx.x;
    const int t = threadIdx.x;      // h index, 256 threads

    // natural layout now: g_red[mtile*32768 + local_row*256 + h]
    float x = g_red[(b >> 7) * 32768 + (b & 127) * H1 + t];

    x += b1[t];
    x = (x >= 0.0f) ? x : SLOPE * x;
    x = (x - rm1[t]) * rsqrtf(rv1[t] + EPSV) * g1[t] + be1[t];
    h1s[t] = x;
    __syncthreads();

    if (t < H2) {
        float a = 0.0f;
#pragma unroll 8
        for (int i = 0; i < H1; i++) a += h1s[i] * W2[i * H2 + t];
        a += b2[t];
        a = (a >= 0.0f) ? a : SLOPE * a;
        a = (a - rm2[t]) * rsqrtf(rv2[t] + EPSV) * g2[t] + be2[t];
        red[t] = a * Wc[t];
    }
    for (int sft = H2 / 2; sft > 0; sft >>= 1) {
        __syncthreads();
        if (t < sft) red[t] += red[t + sft];
    }
    __syncthreads();
    if (t == 0) out[b] = red[0] + bc[0];
}

// ---------------------------------------------------------------------------
extern "C" void kernel_launch(void* const* d_in, const int* in_sizes, int n_in,
                              void* d_out, int out_size) {
    const float* vec1  = (const float*)d_in[0];
    const float* vec2  = (const float*)d_in[1];
    const float* vec3  = (const float*)d_in[2];
    const float* W1    = (const float*)d_in[3];
    const float* b1    = (const float*)d_in[4];
    const float* g1    = (const float*)d_in[5];
    const float* beta1 = (const float*)d_in[6];
    const float* rm1   = (const float*)d_in[7];
    const float* rv1   = (const float*)d_in[8];
    const float* W2    = (const float*)d_in[9];
    const float* b2    = (const float*)d_in[10];
    const float* g2    = (const float*)d_in[11];
    const float* beta2 = (const float*)d_in[12];
    const float* rm2   = (const float*)d_in[13];
    const float* rv2   = (const float*)d_in[14];
    const float* Wc    = (const float*)d_in[15];
    const float* bc    = (const float*)d_in[16];
    float* out = (float*)d_out;

    cudaFuncSetAttribute(k_gemm_mma,
                         cudaFuncAttributeMaxDynamicSharedMemorySize, SM_TOTAL);

    dim3 grid(2, NCHUNKS);   // 148 CTAs = 1 wave
    k_gemm_mma<<<grid, NT, SM_TOTAL>>>(vec1, vec2, vec3, W1);

    k_reduce<<<64, 1024>>>();

    k_epi<<<BATCH, H1>>>(b1, g1, beta1, rm1, rv1, W2, b2, g2, beta2,
                         rm2, rv2, Wc, bc, out);
}

// round 14
// speedup vs baseline: 1.0012x; 1.0012x over previous
#include <cuda_runtime.h>
#include <cstdint>

// ===========================================================================
// CALIBRATION ROUND: exact resubmission of R4 (the 168.0 us measurement) to
// distinguish environment drift (H1) from atomic-tail codegen effects (H2).
//
// FusionModel via mma.sync m16n8k16 fp16.
//   H1pre = x @ W1,  x[b,(i*64+j)*64+k] = v1e[b,i]*v2e[b,j]*v3e[b,k]
//   M=256, N=256, K=262144. Grid: 2 M-tiles x 74 K-chunks = 148 CTAs.
//   Per slab: A (rank-1) computed into SMEM as fp16 from register-resident
//   v3 + per-slab scalar; B = W1 slab via cp.async (fp32, double-buffered,
//   swizzled), packed to fp16 at fragment-load time with RNE. 128x256 CTA
//   tile accumulated in fp32 registers; split-K atomicAdd into g_acc.
// ===========================================================================

namespace {
constexpr int BATCH = 256;
constexpr int DIN   = 63;
constexpr int H1    = 256;
constexpr int H2    = 128;
constexpr float EPSV  = 1e-5f;
constexpr float SLOPE = 0.1f;

constexpr int NSLABS  = 4096;
constexpr int NCHUNKS = 74;
constexpr int NT      = 256;

constexpr int SMB_BYTES = 65536;        // B slab: 64k x 256n fp32 (swizzled)
constexpr int SMA_BYTES = 128 * 144;    // A slab: 128 rows x (64 half + pad)
constexpr int SM_B   = 0;               // 2 x 64 KB
constexpr int SM_A   = 2 * SMB_BYTES;   // 131072, 2 x 18432
constexpr int SM_TOTAL = SM_A + 2 * SMA_BYTES;   // 167936 B
constexpr int A_WSTRIDE = 36;           // words per A row (144 B)
}

__device__ float g_acc[BATCH * H1];

__global__ void k_zero() {
    int i = blockIdx.x * blockDim.x + threadIdx.x;
    if (i < BATCH * H1) g_acc[i] = 0.0f;
}

// ---- helpers --------------------------------------------------------------
__device__ __forceinline__ uint32_t smem_u32(const void* p) {
    uint32_t a;
    asm("{ .reg .u64 t; cvta.to.shared.u64 t, %1; cvt.u32.u64 %0, t; }"
        : "=r"(a) : "l"(p));
    return a;
}
__device__ __forceinline__ uint32_t pkh2(float lo, float hi) {
    uint32_t d;  // d = {lo: cvt(lo), hi: cvt(hi)}; PTX operand order: d, hi, lo
    asm("cvt.rn.f16x2.f32 %0, %1, %2;" : "=r"(d) : "f"(hi), "f"(lo));
    return d;
}
__device__ __forceinline__ void mma_f16(float* c, const uint32_t* a,
                                        const uint32_t* b) {
    asm volatile(
        "mma.sync.aligned.m16n8k16.row.col.f32.f16.f16.f32 "
        "{%0,%1,%2,%3}, {%4,%5,%6,%7}, {%8,%9}, {%0,%1,%2,%3};"
        : "+f"(c[0]), "+f"(c[1]), "+f"(c[2]), "+f"(c[3])
        : "r"(a[0]), "r"(a[1]), "r"(a[2]), "r"(a[3]), "r"(b[0]), "r"(b[1]));
}
__device__ __forceinline__ void cp16(uint32_t dst, const void* src) {
    asm volatile("cp.async.cg.shared.global [%0], [%1], 16;"
                 :: "r"(dst), "l"(src));
}
#define CP_COMMIT() asm volatile("cp.async.commit_group;" ::: "memory")
#define CP_WAIT1()  asm volatile("cp.async.wait_group 1;" ::: "memory")

// swizzled float index of B[k][n] (k:0..63, n:0..255), xor class (k>>1)&3
__device__ __forceinline__ int bidx(int k, int n) {
    return k * 256 + (((n >> 2) ^ (((k >> 1) & 3) << 1)) << 2) + (n & 3);
}

// ---------------------------------------------------------------------------
__global__ __launch_bounds__(NT, 1)
void k_gemm_mma(const float* __restrict__ v1, const float* __restrict__ v2,
                const float* __restrict__ v3, const float* __restrict__ W1) {
    extern __shared__ char smem[];
    float*    Bsm = (float*)(smem + SM_B);
    uint32_t* Asm = (uint32_t*)(smem + SM_A);   // [2][128 rows][36 words]
    const uint32_t b_u32 = smem_u32(Bsm);

    const int tid = threadIdx.x;
    const int wid = tid >> 5, l = tid & 31;
    const int lq = l >> 2, lr = l & 3;
    const int wm = wid >> 2, wn = wid & 3;
    const int mr = wm * 64, nc = wn * 64;

    const int mtile = blockIdx.x;
    const int chunk = blockIdx.y;
    const int s_lo = (chunk * NSLABS) / NCHUNKS;
    const int s_hi = ((chunk + 1) * NSLABS) / NCHUNKS;

    // A-generation assignment: thread owns (row tb, k-half h); v3 in registers
    const int tb = tid >> 1;
    const int h  = tid & 1;
    const int bg = mtile * 128 + tb;
    float v3r[32];
#pragma unroll
    for (int q = 0; q < 32; ++q) {
        int kk = h * 32 + q;
        v3r[q] = (kk < DIN) ? v3[bg * DIN + kk] : 1.0f;
    }

    // ---- cp.async B slab issue ----
    const int ck = tid & 63;
    const int cq = tid >> 6;

    auto issue = [&](int s, int p) {
        const float* base = W1 + (size_t)s * 64 * H1 + (size_t)ck * H1 + cq * 64;
        uint32_t bb = b_u32 + (uint32_t)p * SMB_BYTES;
#pragma unroll
        for (int it = 0; it < 16; ++it) {
            int ncx = cq * 16 + it;
            uint32_t dst = bb + (uint32_t)((ck * 64 + (ncx ^ (((ck >> 1) & 3) << 1))) * 16);
            cp16(dst, base + it * 4);
        }
        CP_COMMIT();
    };

    issue(s_lo, 0);
    if (s_lo + 1 < s_hi) issue(s_lo + 1, 1);

    float acc[4][8][4];
#pragma unroll
    for (int mt = 0; mt < 4; ++mt)
#pragma unroll
        for (int nt = 0; nt < 8; ++nt)
#pragma unroll
            for (int q = 0; q < 4; ++q) acc[mt][nt][q] = 0.0f;

    for (int s = s_lo; s < s_hi; ++s) {
        const int sl = s - s_lo;
        const int p = sl & 1;
        const float*    Bp = Bsm + p * (SMB_BYTES / 4);
        const uint32_t* Ap = Asm + p * (SMA_BYTES / 4);

        // ---- A gen: fp16 A[row][k] = cvt(s(b) * v3[b,k]) ----
        {
            int i = s >> 6, j = s & 63;
            float ai = (i < DIN) ? __ldg(v1 + bg * DIN + i) : 1.0f;
            float cj = (j < DIN) ? __ldg(v2 + bg * DIN + j) : 1.0f;
            float sv = ai * cj;
            uint32_t* dst = (uint32_t*)(smem + SM_A + p * SMA_BYTES) +
                            tb * A_WSTRIDE + h * 16;
#pragma unroll
            for (int g = 0; g < 4; ++g) {
                uint4 v;
                v.x = pkh2(sv * v3r[g * 8 + 0], sv * v3r[g * 8 + 1]);
                v.y = pkh2(sv * v3r[g * 8 + 2], sv * v3r[g * 8 + 3]);
                v.z = pkh2(sv * v3r[g * 8 + 4], sv * v3r[g * 8 + 5]);
                v.w = pkh2(sv * v3r[g * 8 + 6], sv * v3r[g * 8 + 7]);
                *(uint4*)(dst + g * 4) = v;
            }
        }

        CP_WAIT1();
        __syncthreads();

#pragma unroll
        for (int kk = 0; kk < 4; ++kk) {
            const int kw = kk * 8 + lr;     // word offset within A row
            const int kb = kk * 16;         // k base for B
            // A fragments (conflict-free LDS.32 half2)
            uint32_t a[4][4];
#pragma unroll
            for (int mt = 0; mt < 4; ++mt) {
                const uint32_t* ar = Ap + (mr + mt * 16 + lq) * A_WSTRIDE;
                a[mt][0] = ar[kw];
                a[mt][1] = ar[8 * A_WSTRIDE + kw];
                a[mt][2] = ar[kw + 4];
                a[mt][3] = ar[8 * A_WSTRIDE + kw + 4];
            }
            // B fragments (fp32 loads, RNE pack to fp16)
            const int k0 = kb + lr * 2;
            uint32_t bfr[8][2];
#pragma unroll
            for (int nt = 0; nt < 8; ++nt) {
                const int n = nc + nt * 8 + lq;
                bfr[nt][0] = pkh2(Bp[bidx(k0, n)],     Bp[bidx(k0 + 1, n)]);
                bfr[nt][1] = pkh2(Bp[bidx(k0 + 8, n)], Bp[bidx(k0 + 9, n)]);
            }
#pragma unroll
            for (int mt = 0; mt < 4; ++mt)
#pragma unroll
                for (int nt = 0; nt < 8; ++nt)
                    mma_f16(acc[mt][nt], a[mt], bfr[nt]);
        }
        __syncthreads();

        if (s + 2 < s_hi) issue(s + 2, p);
    }

    // ---- split-K reduction ----
#pragma unroll
    for (int mt = 0; mt < 4; ++mt) {
        const int row = mtile * 128 + mr + mt * 16 + lq;
#pragma unroll
        for (int nt = 0; nt < 8; ++nt) {
            const int col = nc + nt * 8 + lr * 2;
            atomicAdd(g_acc + row * H1 + col,           acc[mt][nt][0]);
            atomicAdd(g_acc + row * H1 + col + 1,       acc[mt][nt][1]);
            atomicAdd(g_acc + (row + 8) * H1 + col,     acc[mt][nt][2]);
            atomicAdd(g_acc + (row + 8) * H1 + col + 1, acc[mt][nt][3]);
        }
    }
}

// ---------------------------------------------------------------------------
__global__ __launch_bounds__(H2)
void k_epi(const float* __restrict__ b1,  const float* __restrict__ g1,
           const float* __restrict__ be1, const float* __restrict__ rm1,
           const float* __restrict__ rv1, const float* __restrict__ W2,
           const float* __restrict__ b2,  const float* __restrict__ g2,
           const float* __restrict__ be2, const float* __restrict__ rm2,
           const float* __restrict__ rv2, const float* __restrict__ Wc,
           const float* __restrict__ bc,  float* __restrict__ out) {
    __shared__ float h1s[H1];
    __shared__ float red[H2];
    const int b = blockIdx.x;
    const int t = threadIdx.x;

    for (int hh = t; hh < H1; hh += H2) {
        float x = g_acc[b * H1 + hh] + b1[hh];
        x = (x >= 0.0f) ? x : SLOPE * x;
        x = (x - rm1[hh]) * rsqrtf(rv1[hh] + EPSV) * g1[hh] + be1[hh];
        h1s[hh] = x;
    }
    __syncthreads();

    float a = 0.0f;
#pragma unroll 8
    for (int i = 0; i < H1; i++) a += h1s[i] * W2[i * H2 + t];
    a += b2[t];
    a = (a >= 0.0f) ? a : SLOPE * a;
    a = (a - rm2[t]) * rsqrtf(rv2[t] + EPSV) * g2[t] + be2[t];
    red[t] = a * Wc[t];
    __syncthreads();

    for (int sft = H2 / 2; sft > 0; sft >>= 1) {
        if (t < sft) red[t] += red[t + sft];
        __syncthreads();
    }
    if (t == 0) out[b] = red[0] + bc[0];
}

// ---------------------------------------------------------------------------
extern "C" void kernel_launch(void* const* d_in, const int* in_sizes, int n_in,
                              void* d_out, int out_size) {
    const float* vec1  = (const float*)d_in[0];
    const float* vec2  = (const float*)d_in[1];
    const float* vec3  = (const float*)d_in[2];
    const float* W1    = (const float*)d_in[3];
    const float* b1    = (const float*)d_in[4];
    const float* g1    = (const float*)d_in[5];
    const float* beta1 = (const float*)d_in[6];
    const float* rm1   = (const float*)d_in[7];
    const float* rv1   = (const float*)d_in[8];
    const float* W2    = (const float*)d_in[9];
    const float* b2    = (const float*)d_in[10];
    const float* g2    = (const float*)d_in[11];
    const float* beta2 = (const float*)d_in[12];
    const float* rm2   = (const float*)d_in[13];
    const float* rv2   = (const float*)d_in[14];
    const float* Wc    = (const float*)d_in[15];
    const float* bc    = (const float*)d_in[16];
    float* out = (float*)d_out;

    cudaFuncSetAttribute(k_gemm_mma,
                         cudaFuncAttributeMaxDynamicSharedMemorySize, SM_TOTAL);

    k_zero<<<(BATCH * H1 + 1023) / 1024, 1024>>>();

    dim3 grid(2, NCHUNKS);   // 148 CTAs
    k_gemm_mma<<<grid, NT, SM_TOTAL>>>(vec1, vec2, vec3, W1);

    k_epi<<<BATCH, H2>>>(b1, g1, beta1, rm1, rv1, W2, b2, g2, beta2,
                         rm2, rv2, Wc, bc, out);
}

// round 15
// speedup vs baseline: 1.1171x; 1.1158x over previous
#include <cuda_runtime.h>
#include <cstdint>

// ===========================================================================
// FusionModel via mma.sync m16n8k16 fp16 + ldmatrix — R6 trunk (best real
// measurement) + double-buffered B16/A16 + single barrier per slab.
//   H1pre = x @ W1,  x[b,(i*64+j)*64+k] = v1e[b,i]*v2e[b,j]*v3e[b,k]
//   M=256, N=256, K=262144. Grid: 2 mtiles x 74 K-chunks = 148 CTAs (1 wave).
// Per slab:
//   wait(own cp group) -> convert own B32[p] floats to fp16 B16[p] [k][n]
//   (no barrier needed: each thread converts exactly what it copied);
//   A rank-1 fp16 gen from register v3 -> A16[p]; ONE __syncthreads();
//   issue cp(s+2); mma via ldmatrix.x4 (A) / ldmatrix.x4.trans (B).
// Last-slab cp race closed by a trailing empty commit_group (groups retire
// in commit order, so wait_group 1 then implies the real group landed).
// Tail: R4/R6-proven atomicAdd split-K + k_zero + k_epi.
// ===========================================================================

namespace {
constexpr int BATCH = 256;
constexpr int DIN   = 63;
constexpr int H1    = 256;
constexpr int H2    = 128;
constexpr float EPSV  = 1e-5f;
constexpr float SLOPE = 0.1f;

constexpr int NSLABS  = 4096;
constexpr int NCHUNKS = 74;
constexpr int NT      = 256;

// SMEM map (bytes): 229376 total (fits 228 KB carveout)
constexpr int SMB_BYTES = 65536;                 // one B32 slab
constexpr int SM_B32 = 0;                        // 2 x 64 KB
constexpr int SM_B16 = 2 * SMB_BYTES;            // 131072: 2 x 32 KB fp16 [k][n]
constexpr int SM_A16 = SM_B16 + 2 * 32768;       // 196608: 2 x 16 KB fp16 [m][k]
constexpr int SM_TOTAL = SM_A16 + 2 * 16384;     // 229376
}

__device__ float g_acc[BATCH * H1];

__global__ void k_zero() {
    int i = blockIdx.x * blockDim.x + threadIdx.x;
    if (i < BATCH * H1) g_acc[i] = 0.0f;
}

// ---- helpers --------------------------------------------------------------
__device__ __forceinline__ uint32_t smem_u32(const void* p) {
    uint32_t a;
    asm("{ .reg .u64 t; cvta.to.shared.u64 t, %1; cvt.u32.u64 %0, t; }"
        : "=r"(a) : "l"(p));
    return a;
}
__device__ __forceinline__ uint32_t pkh2(float lo, float hi) {
    uint32_t d;
    asm("cvt.rn.f16x2.f32 %0, %1, %2;" : "=r"(d) : "f"(hi), "f"(lo));
    return d;
}
__device__ __forceinline__ void mma_f16(float* c, const uint32_t* a,
                                        const uint32_t* b) {
    asm volatile(
        "mma.sync.aligned.m16n8k16.row.col.f32.f16.f16.f32 "
        "{%0,%1,%2,%3}, {%4,%5,%6,%7}, {%8,%9}, {%0,%1,%2,%3};"
        : "+f"(c[0]), "+f"(c[1]), "+f"(c[2]), "+f"(c[3])
        : "r"(a[0]), "r"(a[1]), "r"(a[2]), "r"(a[3]), "r"(b[0]), "r"(b[1]));
}
__device__ __forceinline__ void ldsm4(uint32_t* r, uint32_t addr) {
    asm volatile("ldmatrix.sync.aligned.m8n8.x4.shared.b16 {%0,%1,%2,%3}, [%4];"
                 : "=r"(r[0]), "=r"(r[1]), "=r"(r[2]), "=r"(r[3]) : "r"(addr));
}
__device__ __forceinline__ void ldsm4t(uint32_t& r0, uint32_t& r1,
                                       uint32_t& r2, uint32_t& r3, uint32_t addr) {
    asm volatile("ldmatrix.sync.aligned.m8n8.x4.trans.shared.b16 {%0,%1,%2,%3}, [%4];"
                 : "=r"(r0), "=r"(r1), "=r"(r2), "=r"(r3) : "r"(addr));
}
__device__ __forceinline__ void cp16(uint32_t dst, const void* src) {
    asm volatile("cp.async.cg.shared.global [%0], [%1], 16;"
                 :: "r"(dst), "l"(src));
}
#define CP_COMMIT() asm volatile("cp.async.commit_group;" ::: "memory")
#define CP_WAIT1()  asm volatile("cp.async.wait_group 1;" ::: "memory")

// ---------------------------------------------------------------------------
__global__ __launch_bounds__(NT, 1)
void k_gemm_mma(const float* __restrict__ v1, const float* __restrict__ v2,
                const float* __restrict__ v3, const float* __restrict__ W1) {
    extern __shared__ char smem[];
    const uint32_t sbase   = smem_u32(smem);
    const uint32_t b32_u32 = sbase + SM_B32;
    const uint32_t b16_u32 = sbase + SM_B16;
    const uint32_t a16_u32 = sbase + SM_A16;

    const int tid = threadIdx.x;
    const int wid = tid >> 5, l = tid & 31;
    const int wm = wid >> 2, wn = wid & 3;
    const int mr = wm * 64, ncol = wn * 64;

    const int mtile = blockIdx.x;
    const int chunk = blockIdx.y;
    const int s_lo = (chunk * NSLABS) / NCHUNKS;
    const int s_hi = ((chunk + 1) * NSLABS) / NCHUNKS;

    // A-gen ownership: row tb, k-half hh; v3 register-resident (R6 scheme)
    const int tb = tid >> 1, hh = tid & 1;
    const int bg = mtile * 128 + tb;
    float v3r[32];
#pragma unroll
    for (int q = 0; q < 32; ++q) {
        int kk = hh * 32 + q;
        v3r[q] = (kk < DIN) ? v3[bg * DIN + kk] : 1.0f;
    }

    // cp/convert ownership: row ck (0..63), n-window cq*64
    const int ck = tid & 63;        // ck&7 == l&7 -> conflict-free phases
    const int cq = tid >> 6;

    auto issue = [&](int s, int p) {
        const float* base = W1 + (size_t)s * 64 * H1 + (size_t)ck * H1 + cq * 64;
        uint32_t bb = b32_u32 + (uint32_t)p * SMB_BYTES;
#pragma unroll
        for (int it = 0; it < 16; ++it) {
            int nc = cq * 16 + it;
            uint32_t dst = bb + (uint32_t)((ck * 64 + (nc ^ (ck & 7))) * 16);
            cp16(dst, base + it * 4);
        }
        CP_COMMIT();
    };

    issue(s_lo, 0);
    if (s_lo + 1 < s_hi) issue(s_lo + 1, 1);

    float acc[4][8][4];
#pragma unroll
    for (int mt = 0; mt < 4; ++mt)
#pragma unroll
        for (int nt = 0; nt < 8; ++nt)
#pragma unroll
            for (int q = 0; q < 4; ++q) acc[mt][nt][q] = 0.0f;

    // per-lane ldmatrix address components (verified R5/R6)
    const int arow_off = (l & 7) | (((l >> 3) & 1) << 3);
    const int akadd    = l >> 4;
    const int bk_off   = ((l >> 3) & 1) * 8 + (l & 7);
    const int bncadd   = l >> 4;

    for (int s = s_lo; s < s_hi; ++s) {
        const int sl = s - s_lo;
        const int p = sl & 1;
        const uint32_t b16p = b16_u32 + p * 32768;
        const uint32_t a16p = a16_u32 + p * 16384;

        // ---- wait own cp group(s); convert own floats fp32 -> fp16 [k][n]
        //      (no barrier: each thread converts exactly what it copied) ----
        CP_WAIT1();
        {
            const char* src = smem + SM_B32 + p * SMB_BYTES;
            char* d16 = smem + (SM_B16 + p * 32768);
#pragma unroll
            for (int g = 0; g < 8; ++g) {
                int nc0 = cq * 16 + g * 2;
                float4 f0 = *(const float4*)(src + (ck * 64 + ((nc0)     ^ (ck & 7))) * 16);
                float4 f1 = *(const float4*)(src + (ck * 64 + ((nc0 + 1) ^ (ck & 7))) * 16);
                uint4 h;
                h.x = pkh2(f0.x, f0.y);
                h.y = pkh2(f0.z, f0.w);
                h.z = pkh2(f1.x, f1.y);
                h.w = pkh2(f1.z, f1.w);
                int ncc = cq * 8 + g;
                *(uint4*)(d16 + (ck * 32 + (ncc ^ (ck & 7))) * 16) = h;
            }
        }

        // ---- A gen: fp16 A[m][k] = cvt(s(b) * v3[b,k]), swizzled chunks ----
        {
            int i = s >> 6, j = s & 63;
            float ai = (i < DIN) ? __ldg(v1 + bg * DIN + i) : 1.0f;
            float cj = (j < DIN) ? __ldg(v2 + bg * DIN + j) : 1.0f;
            float sv = ai * cj;
            char* ad = smem + (SM_A16 + p * 16384);
#pragma unroll
            for (int g = 0; g < 4; ++g) {
                uint4 v;
                v.x = pkh2(sv * v3r[g * 8 + 0], sv * v3r[g * 8 + 1]);
                v.y = pkh2(sv * v3r[g * 8 + 2], sv * v3r[g * 8 + 3]);
                v.z = pkh2(sv * v3r[g * 8 + 4], sv * v3r[g * 8 + 5]);
                v.w = pkh2(sv * v3r[g * 8 + 6], sv * v3r[g * 8 + 7]);
                int cc = hh * 4 + g;
                *(uint4*)(ad + (tb * 8 + (cc ^ (tb & 7))) * 16) = v;
            }
        }

        __syncthreads();   // B16[p]/A16[p] ready; prior mma done with B32[p]

        // next cp overlaps this slab's mma; empty commit on the tail keeps
        // in-order group retirement honest for the final CP_WAIT1
        if (s + 2 < s_hi) issue(s + 2, p); else CP_COMMIT();

        // ---- mma over 4 k16 steps (ldmatrix fragments, verified R5/R6) ----
#pragma unroll
        for (int kk = 0; kk < 4; ++kk) {
            uint32_t a[4][4];
#pragma unroll
            for (int mt = 0; mt < 4; ++mt) {
                uint32_t addr = a16p +
                    (uint32_t)((mr + mt * 16 + arow_off) * 128 +
                               (((kk * 2 + akadd) ^ (l & 7)) * 16));
                ldsm4(a[mt], addr);
            }
            uint32_t bfr[8][2];
#pragma unroll
            for (int q = 0; q < 4; ++q) {
                int krow = kk * 16 + bk_off;
                int ncc = ((ncol + q * 16) >> 3) + bncadd;
                uint32_t addr = b16p +
                    (uint32_t)((krow * 32 + (ncc ^ (krow & 7))) * 16);
                ldsm4t(bfr[2 * q][0], bfr[2 * q][1],
                       bfr[2 * q + 1][0], bfr[2 * q + 1][1], addr);
            }
#pragma unroll
            for (int mt = 0; mt < 4; ++mt)
#pragma unroll
                for (int nt = 0; nt < 8; ++nt)
                    mma_f16(acc[mt][nt], a[mt], bfr[nt]);
        }
    }

    // ---- split-K reduction (proven tail) ----
    const int lq = l >> 2, lr = l & 3;
#pragma unroll
    for (int mt = 0; mt < 4; ++mt) {
        const int row = mtile * 128 + mr + mt * 16 + lq;
#pragma unroll
        for (int nt = 0; nt < 8; ++nt) {
            const int col = ncol + nt * 8 + lr * 2;
            atomicAdd(g_acc + row * H1 + col,           acc[mt][nt][0]);
            atomicAdd(g_acc + row * H1 + col + 1,       acc[mt][nt][1]);
            atomicAdd(g_acc + (row + 8) * H1 + col,     acc[mt][nt][2]);
            atomicAdd(g_acc + (row + 8) * H1 + col + 1, acc[mt][nt][3]);
        }
    }
}

// ---------------------------------------------------------------------------
__global__ __launch_bounds__(H2)
void k_epi(const float* __restrict__ b1,  const float* __restrict__ g1,
           const float* __restrict__ be1, const float* __restrict__ rm1,
           const float* __restrict__ rv1, const float* __restrict__ W2,
           const float* __restrict__ b2,  const float* __restrict__ g2,
           const float* __restrict__ be2, const float* __restrict__ rm2,
           const float* __restrict__ rv2, const float* __restrict__ Wc,
           const float* __restrict__ bc,  float* __restrict__ out) {
    __shared__ float h1s[H1];
    __shared__ float red[H2];
    const int b = blockIdx.x;
    const int t = threadIdx.x;

    for (int h = t; h < H1; h += H2) {
        float x = g_acc[b * H1 + h] + b1[h];
        x = (x >= 0.0f) ? x : SLOPE * x;
        x = (x - rm1[h]) * rsqrtf(rv1[h] + EPSV) * g1[h] + be1[h];
        h1s[h] = x;
    }
    __syncthreads();

    float a = 0.0f;
#pragma unroll 8
    for (int i = 0; i < H1; i++) a += h1s[i] * W2[i * H2 + t];
    a += b2[t];
    a = (a >= 0.0f) ? a : SLOPE * a;
    a = (a - rm2[t]) * rsqrtf(rv2[t] + EPSV) * g2[t] + be2[t];
    red[t] = a * Wc[t];
    __syncthreads();

    for (int sft = H2 / 2; sft > 0; sft >>= 1) {
        if (t < sft) red[t] += red[t + sft];
        __syncthreads();
    }
    if (t == 0) out[b] = red[0] + bc[0];
}

// ---------------------------------------------------------------------------
extern "C" void kernel_launch(void* const* d_in, const int* in_sizes, int n_in,
                              void* d_out, int out_size) {
    const float* vec1  = (const float*)d_in[0];
    const float* vec2  = (const float*)d_in[1];
    const float* vec3  = (const float*)d_in[2];
    const float* W1    = (const float*)d_in[3];
    const float* b1    = (const float*)d_in[4];
    const float* g1    = (const float*)d_in[5];
    const float* beta1 = (const float*)d_in[6];
    const float* rm1   = (const float*)d_in[7];
    const float* rv1   = (const float*)d_in[8];
    const float* W2    = (const float*)d_in[9];
    const float* b2    = (const float*)d_in[10];
    const float* g2    = (const float*)d_in[11];
    const float* beta2 = (const float*)d_in[12];
    const float* rm2   = (const float*)d_in[13];
    const float* rv2   = (const float*)d_in[14];
    const float* Wc    = (const float*)d_in[15];
    const float* bc    = (const float*)d_in[16];
    float* out = (float*)d_out;

    cudaFuncSetAttribute(k_gemm_mma,
                         cudaFuncAttributeMaxDynamicSharedMemorySize, SM_TOTAL);

    k_zero<<<(BATCH * H1 + 1023) / 1024, 1024>>>();

    dim3 grid(2, NCHUNKS);   // 148 CTAs = 1 wave
    k_gemm_mma<<<grid, NT, SM_TOTAL>>>(vec1, vec2, vec3, W1);

    k_epi<<<BATCH, H2>>>(b1, g1, beta1, rm1, rv1, W2, b2, g2, beta2,
                         rm2, rv2, Wc, bc, out);
}

// round 16
// speedup vs baseline: 1.9967x; 1.7873x over previous
#include <cuda_runtime.h>
#include <cstdint>

// ===========================================================================
// FusionModel via mma.sync m16n8k16 fp16 + ldmatrix — R15 trunk with ONE
// change: cp.async pattern coalesced (row-contiguous per warp, 4 wavefronts
// per instruction instead of 32) + matching convert ownership.
//   H1pre = x @ W1,  x[b,(i*64+j)*64+k] = v1e[b,i]*v2e[b,j]*v3e[b,k]
//   M=256, N=256, K=262144. Grid: 2 mtiles x 74 K-chunks = 148 CTAs (1 wave).
// Per slab: wait(own cp) -> convert own B32[p] -> A-gen -> one sync ->
//   issue cp(s+2) -> mma via ldmatrix. B16 layout identical to R15.
// Tail: proven atomicAdd split-K + k_zero + k_epi.
// ===========================================================================

namespace {
constexpr int BATCH = 256;
constexpr int DIN   = 63;
constexpr int H1    = 256;
constexpr int H2    = 128;
constexpr float EPSV  = 1e-5f;
constexpr float SLOPE = 0.1f;

constexpr int NSLABS  = 4096;
constexpr int NCHUNKS = 74;
constexpr int NT      = 256;

// SMEM map (bytes): 229376 total
constexpr int SMB_BYTES = 65536;                 // one B32 slab
constexpr int SM_B32 = 0;                        // 2 x 64 KB
constexpr int SM_B16 = 2 * SMB_BYTES;            // 131072: 2 x 32 KB fp16 [k][n]
constexpr int SM_A16 = SM_B16 + 2 * 32768;       // 196608: 2 x 16 KB fp16 [m][k]
constexpr int SM_TOTAL = SM_A16 + 2 * 16384;     // 229376
}

__device__ float g_acc[BATCH * H1];

__global__ void k_zero() {
    int i = blockIdx.x * blockDim.x + threadIdx.x;
    if (i < BATCH * H1) g_acc[i] = 0.0f;
}

// ---- helpers --------------------------------------------------------------
__device__ __forceinline__ uint32_t smem_u32(const void* p) {
    uint32_t a;
    asm("{ .reg .u64 t; cvta.to.shared.u64 t, %1; cvt.u32.u64 %0, t; }"
        : "=r"(a) : "l"(p));
    return a;
}
__device__ __forceinline__ uint32_t pkh2(float lo, float hi) {
    uint32_t d;
    asm("cvt.rn.f16x2.f32 %0, %1, %2;" : "=r"(d) : "f"(hi), "f"(lo));
    return d;
}
__device__ __forceinline__ void mma_f16(float* c, const uint32_t* a,
                                        const uint32_t* b) {
    asm volatile(
        "mma.sync.aligned.m16n8k16.row.col.f32.f16.f16.f32 "
        "{%0,%1,%2,%3}, {%4,%5,%6,%7}, {%8,%9}, {%0,%1,%2,%3};"
        : "+f"(c[0]), "+f"(c[1]), "+f"(c[2]), "+f"(c[3])
        : "r"(a[0]), "r"(a[1]), "r"(a[2]), "r"(a[3]), "r"(b[0]), "r"(b[1]));
}
__device__ __forceinline__ void ldsm4(uint32_t* r, uint32_t addr) {
    asm volatile("ldmatrix.sync.aligned.m8n8.x4.shared.b16 {%0,%1,%2,%3}, [%4];"
                 : "=r"(r[0]), "=r"(r[1]), "=r"(r[2]), "=r"(r[3]) : "r"(addr));
}
__device__ __forceinline__ void ldsm4t(uint32_t& r0, uint32_t& r1,
                                       uint32_t& r2, uint32_t& r3, uint32_t addr) {
    asm volatile("ldmatrix.sync.aligned.m8n8.x4.trans.shared.b16 {%0,%1,%2,%3}, [%4];"
                 : "=r"(r0), "=r"(r1), "=r"(r2), "=r"(r3) : "r"(addr));
}
__device__ __forceinline__ void cp16(uint32_t dst, const void* src) {
    asm volatile("cp.async.cg.shared.global [%0], [%1], 16;"
                 :: "r"(dst), "l"(src));
}
#define CP_COMMIT() asm volatile("cp.async.commit_group;" ::: "memory")
#define CP_WAIT1()  asm volatile("cp.async.wait_group 1;" ::: "memory")

// ---------------------------------------------------------------------------
__global__ __launch_bounds__(NT, 1)
void k_gemm_mma(const float* __restrict__ v1, const float* __restrict__ v2,
                const float* __restrict__ v3, const float* __restrict__ W1) {
    extern __shared__ char smem[];
    const uint32_t sbase   = smem_u32(smem);
    const uint32_t b32_u32 = sbase + SM_B32;
    const uint32_t b16_u32 = sbase + SM_B16;
    const uint32_t a16_u32 = sbase + SM_A16;

    const int tid = threadIdx.x;
    const int wid = tid >> 5, l = tid & 31;
    const int wm = wid >> 2, wn = wid & 3;
    const int mr = wm * 64, ncol = wn * 64;

    const int mtile = blockIdx.x;
    const int chunk = blockIdx.y;
    const int s_lo = (chunk * NSLABS) / NCHUNKS;
    const int s_hi = ((chunk + 1) * NSLABS) / NCHUNKS;

    // A-gen ownership: row tb, k-half hh; v3 register-resident
    const int tb = tid >> 1, hh = tid & 1;
    const int bg = mtile * 128 + tb;
    float v3r[32];
#pragma unroll
    for (int q = 0; q < 32; ++q) {
        int kk = hh * 32 + q;
        v3r[q] = (kk < DIN) ? v3[bg * DIN + kk] : 1.0f;
    }

    // ---- COALESCED cp ownership: warp wid owns k-rows wid*8..wid*8+7.
    //      Instruction i: row = wid*8 + (i>>1); lanes cover 512B contiguous
    //      (chunks nc = (i&1)*32 + l) -> 4 L1 wavefronts per instruction. ----
    const int wrow = wid * 8;

    auto issue = [&](int s, int p) {
        const float* wbase = W1 + (size_t)s * 64 * H1;
        uint32_t bb = b32_u32 + (uint32_t)p * SMB_BYTES;
#pragma unroll
        for (int i = 0; i < 16; ++i) {
            int row = wrow + (i >> 1);
            int nc  = (i & 1) * 32 + l;
            uint32_t dst = bb + (uint32_t)((row * 64 + (nc ^ (row & 7))) * 16);
            cp16(dst, wbase + (size_t)row * H1 + nc * 4);
        }
        CP_COMMIT();
    };

    issue(s_lo, 0);
    if (s_lo + 1 < s_hi) issue(s_lo + 1, 1);

    float acc[4][8][4];
#pragma unroll
    for (int mt = 0; mt < 4; ++mt)
#pragma unroll
        for (int nt = 0; nt < 8; ++nt)
#pragma unroll
            for (int q = 0; q < 4; ++q) acc[mt][nt][q] = 0.0f;

    // per-lane ldmatrix address components (verified R5/R6/R15)
    const int arow_off = (l & 7) | (((l >> 3) & 1) << 3);
    const int akadd    = l >> 4;
    const int bk_off   = ((l >> 3) & 1) * 8 + (l & 7);
    const int bncadd   = l >> 4;

    for (int s = s_lo; s < s_hi; ++s) {
        const int sl = s - s_lo;
        const int p = sl & 1;
        const uint32_t b16p = b16_u32 + p * 32768;
        const uint32_t a16p = a16_u32 + p * 16384;

        // ---- wait own cp group; convert own floats fp32 -> fp16 [k][n]
        //      thread owns rows wrow..wrow+7, fp32 chunks {l, l+32} ----
        CP_WAIT1();
        {
            const char* src = smem + SM_B32 + p * SMB_BYTES;
            char* d16 = smem + (SM_B16 + p * 32768);
#pragma unroll
            for (int rr = 0; rr < 8; ++rr) {
                const int row = wrow + rr;
                const int x = row & 7;
                float4 f0 = *(const float4*)(src + (row * 64 + (l ^ x)) * 16);
                float4 f1 = *(const float4*)(src + (row * 64 + ((l + 32) ^ x)) * 16);
                // B16 chunk for fp32 chunk c: idx (c>>1)^x, byte off (c&1)*8
                uint2 h0 = make_uint2(pkh2(f0.x, f0.y), pkh2(f0.z, f0.w));
                uint2 h1 = make_uint2(pkh2(f1.x, f1.y), pkh2(f1.z, f1.w));
                char* rowd = d16 + row * 512;
                *(uint2*)(rowd + (((l >> 1)) ^ x) * 16 + (l & 1) * 8)      = h0;
                *(uint2*)(rowd + (((l >> 1) + 16) ^ x) * 16 + (l & 1) * 8) = h1;
            }
        }

        // ---- A gen: fp16 A[m][k] = cvt(s(b) * v3[b,k]), swizzled chunks ----
        {
            int i = s >> 6, j = s & 63;
            float ai = (i < DIN) ? __ldg(v1 + bg * DIN + i) : 1.0f;
            float cj = (j < DIN) ? __ldg(v2 + bg * DIN + j) : 1.0f;
            float sv = ai * cj;
            char* ad = smem + (SM_A16 + p * 16384);
#pragma unroll
            for (int g = 0; g < 4; ++g) {
                uint4 v;
                v.x = pkh2(sv * v3r[g * 8 + 0], sv * v3r[g * 8 + 1]);
                v.y = pkh2(sv * v3r[g * 8 + 2], sv * v3r[g * 8 + 3]);
                v.z = pkh2(sv * v3r[g * 8 + 4], sv * v3r[g * 8 + 5]);
                v.w = pkh2(sv * v3r[g * 8 + 6], sv * v3r[g * 8 + 7]);
                int cc = hh * 4 + g;
                *(uint4*)(ad + (tb * 8 + (cc ^ (tb & 7))) * 16) = v;
            }
        }

        __syncthreads();   // B16[p]/A16[p] ready; prior mma done with B32[p]

        if (s + 2 < s_hi) issue(s + 2, p); else CP_COMMIT();

        // ---- mma over 4 k16 steps (ldmatrix fragments, unchanged) ----
#pragma unroll
        for (int kk = 0; kk < 4; ++kk) {
            uint32_t a[4][4];
#pragma unroll
            for (int mt = 0; mt < 4; ++mt) {
                uint32_t addr = a16p +
                    (uint32_t)((mr + mt * 16 + arow_off) * 128 +
                               (((kk * 2 + akadd) ^ (l & 7)) * 16));
                ldsm4(a[mt], addr);
            }
            uint32_t bfr[8][2];
#pragma unroll
            for (int q = 0; q < 4; ++q) {
                int krow = kk * 16 + bk_off;
                int ncc = ((ncol + q * 16) >> 3) + bncadd;
                uint32_t addr = b16p +
                    (uint32_t)((krow * 32 + (ncc ^ (krow & 7))) * 16);
                ldsm4t(bfr[2 * q][0], bfr[2 * q][1],
                       bfr[2 * q + 1][0], bfr[2 * q + 1][1], addr);
            }
#pragma unroll
            for (int mt = 0; mt < 4; ++mt)
#pragma unroll
                for (int nt = 0; nt < 8; ++nt)
                    mma_f16(acc[mt][nt], a[mt], bfr[nt]);
        }
    }

    // ---- split-K reduction (proven tail) ----
    const int lq = l >> 2, lr = l & 3;
#pragma unroll
    for (int mt = 0; mt < 4; ++mt) {
        const int row = mtile * 128 + mr + mt * 16 + lq;
#pragma unroll
        for (int nt = 0; nt < 8; ++nt) {
            const int col = ncol + nt * 8 + lr * 2;
            atomicAdd(g_acc + row * H1 + col,           acc[mt][nt][0]);
            atomicAdd(g_acc + row * H1 + col + 1,       acc[mt][nt][1]);
            atomicAdd(g_acc + (row + 8) * H1 + col,     acc[mt][nt][2]);
            atomicAdd(g_acc + (row + 8) * H1 + col + 1, acc[mt][nt][3]);
        }
    }
}

// ---------------------------------------------------------------------------
__global__ __launch_bounds__(H2)
void k_epi(const float* __restrict__ b1,  const float* __restrict__ g1,
           const float* __restrict__ be1, const float* __restrict__ rm1,
           const float* __restrict__ rv1, const float* __restrict__ W2,
           const float* __restrict__ b2,  const float* __restrict__ g2,
           const float* __restrict__ be2, const float* __restrict__ rm2,
           const float* __restrict__ rv2, const float* __restrict__ Wc,
           const float* __restrict__ bc,  float* __restrict__ out) {
    __shared__ float h1s[H1];
    __shared__ float red[H2];
    const int b = blockIdx.x;
    const int t = threadIdx.x;

    for (int h = t; h < H1; h += H2) {
        float x = g_acc[b * H1 + h] + b1[h];
        x = (x >= 0.0f) ? x : SLOPE * x;
        x = (x - rm1[h]) * rsqrtf(rv1[h] + EPSV) * g1[h] + be1[h];
        h1s[h] = x;
    }
    __syncthreads();

    float a = 0.0f;
#pragma unroll 8
    for (int i = 0; i < H1; i++) a += h1s[i] * W2[i * H2 + t];
    a += b2[t];
    a = (a >= 0.0f) ? a : SLOPE * a;
    a = (a - rm2[t]) * rsqrtf(rv2[t] + EPSV) * g2[t] + be2[t];
    red[t] = a * Wc[t];
    __syncthreads();

    for (int sft = H2 / 2; sft > 0; sft >>= 1) {
        if (t < sft) red[t] += red[t + sft];
        __syncthreads();
    }
    if (t == 0) out[b] = red[0] + bc[0];
}

// ---------------------------------------------------------------------------
extern "C" void kernel_launch(void* const* d_in, const int* in_sizes, int n_in,
                              void* d_out, int out_size) {
    const float* vec1  = (const float*)d_in[0];
    const float* vec2  = (const float*)d_in[1];
    const float* vec3  = (const float*)d_in[2];
    const float* W1    = (const float*)d_in[3];
    const float* b1    = (const float*)d_in[4];
    const float* g1    = (const float*)d_in[5];
    const float* beta1 = (const float*)d_in[6];
    const float* rm1   = (const float*)d_in[7];
    const float* rv1   = (const float*)d_in[8];
    const float* W2    = (const float*)d_in[9];
    const float* b2    = (const float*)d_in[10];
    const float* g2    = (const float*)d_in[11];
    const float* beta2 = (const float*)d_in[12];
    const float* rm2   = (const float*)d_in[13];
    const float* rv2   = (const float*)d_in[14];
    const float* Wc    = (const float*)d_in[15];
    const float* bc    = (const float*)d_in[16];
    float* out = (float*)d_out;

    cudaFuncSetAttribute(k_gemm_mma,
                         cudaFuncAttributeMaxDynamicSharedMemorySize, SM_TOTAL);

    k_zero<<<(BATCH * H1 + 1023) / 1024, 1024>>>();

    dim3 grid(2, NCHUNKS);   // 148 CTAs = 1 wave
    k_gemm_mma<<<grid, NT, SM_TOTAL>>>(vec1, vec2, vec3, W1);

    k_epi<<<BATCH, H2>>>(b1, g1, beta1, rm1, rv1, W2, b2, g2, beta2,
                         rm2, rv2, Wc, bc, out);
}